// round 12
// baseline (speedup 1.0000x reference)
#include <cuda_runtime.h>
#include <math.h>

typedef unsigned long long ull;
#define FULLMASK 0xffffffffu

// Per-batch 2x3 matrix M = Ginv * V^T, layout [b][k][c]
__device__ float g_M[3072 * 6];
// Partial sums: [half][batch][f]
__device__ float g_part[2 * 3072 * 6];

__device__ __forceinline__ ull pack2(float lo, float hi) {
    ull r;
    asm("mov.b64 %0, {%1, %2};" : "=l"(r) : "f"(lo), "f"(hi));
    return r;
}
__device__ __forceinline__ void fma2(ull& d, ull a, ull b) {
    asm("fma.rn.f32x2 %0, %1, %2, %0;" : "+l"(d) : "l"(a), "l"(b));
}
__device__ __forceinline__ void unpack2(ull v, float& lo, float& hi) {
    asm("mov.b64 {%0, %1}, %2;" : "=f"(lo), "=f"(hi) : "l"(v));
}

// ---------------------------------------------------------------------------
// Kernel A1: partial per-batch reductions over HALF the k range, 4 batches
// per CTA (acc[4][6] = 24 regs -> high occupancy). grid = 1536:
// blockIdx.x>>1 selects the 4-batch group, &1 selects the k-half.
// ---------------------------------------------------------------------------
__global__ __launch_bounds__(256) void reduce_part_kernel(
    const float* __restrict__ x, const float* __restrict__ w1,
    const float* __restrict__ w2) {
    __shared__ float ws[12288];  // [6][2048] weight chunk; reused for reduction
    const int tid = threadIdx.x;
    const int gb = blockIdx.x >> 1;
    const int half = blockIdx.x & 1;
    const int b0 = gb * 4;

    float acc[4][6];
#pragma unroll
    for (int i = 0; i < 4; i++)
#pragma unroll
        for (int f = 0; f < 6; f++) acc[i][f] = 0.0f;

    // hoisted, incremented x pointers (kills per-iter IMAD address math)
    const float* xp0 = x + (b0 + 0) * 12288 + half * 6144 + tid;
    const float* xp1 = xp0 + 12288;
    const float* xp2 = xp1 + 12288;
    const float* xp3 = xp2 + 12288;

    for (int chh = 0; chh < 3; chh++) {
        const int kbase = (half * 3 + chh) * 2048;
        __syncthreads();
        for (int i = tid; i < 12288; i += 256) {
            int f = i >> 11;
            int kk = i & 2047;
            const float* wsrc = (f < 3) ? w1 : w2;
            int fc = (f < 3) ? f : f - 3;
            ws[i] = __ldg(wsrc + (kbase + kk) * 3 + fc);
        }
        __syncthreads();
#pragma unroll 2
        for (int i = 0; i < 2048; i += 256) {
            int kk = i + tid;
            float wv[6];
#pragma unroll
            for (int f = 0; f < 6; f++) wv[f] = ws[f * 2048 + kk];
            float x0 = __ldg(xp0), x1 = __ldg(xp1), x2 = __ldg(xp2), x3 = __ldg(xp3);
            xp0 += 256; xp1 += 256; xp2 += 256; xp3 += 256;
#pragma unroll
            for (int f = 0; f < 6; f++) {
                acc[0][f] = fmaf(x0, wv[f], acc[0][f]);
                acc[1][f] = fmaf(x1, wv[f], acc[1][f]);
                acc[2][f] = fmaf(x2, wv[f], acc[2][f]);
                acc[3][f] = fmaf(x3, wv[f], acc[3][f]);
            }
        }
    }
    __syncthreads();

    const int lane = tid & 31, wid = tid >> 5;
#pragma unroll
    for (int bb = 0; bb < 4; bb++)
#pragma unroll
        for (int f = 0; f < 6; f++) {
            float v = acc[bb][f];
            v += __shfl_down_sync(FULLMASK, v, 16);
            v += __shfl_down_sync(FULLMASK, v, 8);
            v += __shfl_down_sync(FULLMASK, v, 4);
            v += __shfl_down_sync(FULLMASK, v, 2);
            v += __shfl_down_sync(FULLMASK, v, 1);
            if (lane == 0) ws[wid * 24 + bb * 6 + f] = v;
        }
    __syncthreads();
    if (tid < 24) {
        float s = 0.0f;
#pragma unroll
        for (int w = 0; w < 8; w++) s += ws[w * 24 + tid];
        g_part[half * 18432 + (b0 + tid / 6) * 6 + tid % 6] = s;
    }
}

// ---------------------------------------------------------------------------
// Kernel A2: combine halves + bias, per-batch 2x2 algebra -> M. 3072 threads.
// ---------------------------------------------------------------------------
__global__ __launch_bounds__(256) void finalize_kernel(
    const float* __restrict__ b1, const float* __restrict__ b2) {
    int b = blockIdx.x * 256 + threadIdx.x;
    if (b >= 3072) return;
    float V0[3], V1[3];
    float s0 = 1e-6f, s1 = 1e-6f;
#pragma unroll
    for (int c = 0; c < 3; c++) {
        V0[c] = g_part[b * 6 + c] + g_part[18432 + b * 6 + c] + __ldg(b1 + c);
        V1[c] = g_part[b * 6 + 3 + c] + g_part[18432 + b * 6 + 3 + c] + __ldg(b2 + c);
        s0 += fabsf(V0[c]);
        s1 += fabsf(V1[c]);
    }
    float r0 = 1.0f / s0, r1 = 1.0f / s1;
    float G00 = 0.f, G01 = 0.f, G11 = 0.f;
#pragma unroll
    for (int c = 0; c < 3; c++) {
        V0[c] *= r0;
        V1[c] *= r1;
        G00 += V0[c] * V0[c];
        G01 += V0[c] * V1[c];
        G11 += V1[c] * V1[c];
    }
    float det = G00 * G11 - G01 * G01;
    float rdet = 1.0f / det;
    float i00 = G11 * rdet, i01 = -G01 * rdet, i11 = G00 * rdet;
#pragma unroll
    for (int c = 0; c < 3; c++) {
        g_M[b * 6 + c]     = i00 * V0[c] + i01 * V1[c];
        g_M[b * 6 + 3 + c] = i01 * V0[c] + i11 * V1[c];
    }
}

// ---------------------------------------------------------------------------
// Kernel C (R6-validated, 79.8us): one CTA (256 thr) per HALF output image.
// grid = 4096. Phase 1: rec = M x via LDG.128 into planar smem rec[3][64][32].
// Phase 2: 32-tap circulant Hilbert along h, 4 h-rows per thread, float4 tap
//          table (1 LDS.128 = 4 taps), fma.rn.f32x2, 3x STG.128 cell stores.
// ---------------------------------------------------------------------------
#define PLANEH 2056  // 64*32 + 8 pad (floats)

__global__ __launch_bounds__(256, 4) void fuse_kernel(const float* __restrict__ x,
                                                      float* __restrict__ out) {
    __shared__ float rec_s[3 * PLANEH];
    __shared__ float4 tq[64];  // {t[k], t[k+16], t[k+32], t[k+48]}
    const int gi = blockIdx.x;
    const int g = gi >> 1;
    const int s = gi & 1;
    const int tid = threadIdx.x;

    if (tid < 64) {
        float tv[4];
#pragma unroll
        for (int m = 0; m < 4; m++) {
            int k = (tid + 16 * m) & 63;
            float v = 0.0f;
            if (k & 1) {
                float a = 3.14159265358979323846f * (float)k / 64.0f;
                v = 0.03125f * (cosf(a) / sinf(a));
            }
            tv[m] = v;
        }
        float4 q; q.x = tv[0]; q.y = tv[1]; q.z = tv[2]; q.w = tv[3];
        tq[tid] = q;
    }

    const int b0 = (g * 3) >> 1;  // (g*12288)>>13
    float M0[6], M1[6];
#pragma unroll
    for (int i = 0; i < 6; i++) {
        M0[i] = __ldg(g_M + b0 * 6 + i);
        M1[i] = __ldg(g_M + (b0 + 1) * 6 + i);
    }

    // ---- phase 1: 768 chunks of 4 spatial positions (12 floats, 3x LDG.128)
#pragma unroll
    for (int it = 0; it < 3; it++) {
        int ci = tid + it * 256;
        int h = ci / 12;
        int cc = ci - h * 12;
        int jp0 = s * 96 + cc * 8;          // j offset within row (even)
        int F = g * 12288 + h * 192 + jp0;  // global flat index
        int b = F >> 13;
        int n0 = (F & 8191) >> 1;
        const float4* xp = (const float4*)(x + b * 12288 + 3 * n0);
        float4 q0 = __ldg(xp), q1 = __ldg(xp + 1), q2 = __ldg(xp + 2);
        float xv[12];
        xv[0] = q0.x; xv[1] = q0.y; xv[2]  = q0.z; xv[3]  = q0.w;
        xv[4] = q1.x; xv[5] = q1.y; xv[6]  = q1.z; xv[7]  = q1.w;
        xv[8] = q2.x; xv[9] = q2.y; xv[10] = q2.z; xv[11] = q2.w;
        bool useB = (b != b0);
        float m0 = useB ? M1[0] : M0[0];
        float m1 = useB ? M1[1] : M0[1];
        float m2 = useB ? M1[2] : M0[2];
        float m3 = useB ? M1[3] : M0[3];
        float m4 = useB ? M1[4] : M0[4];
        float m5 = useB ? M1[5] : M0[5];
        float* rowp = rec_s + h * 32 - 32 * s;
#pragma unroll
        for (int nn = 0; nn < 4; nn++) {
            float x0 = xv[3 * nn], x1 = xv[3 * nn + 1], x2 = xv[3 * nn + 2];
            float v0 = m0 * x0 + m1 * x1 + m2 * x2;
            float v1 = m3 * x0 + m4 * x1 + m5 * x2;
            int jpn = jp0 + 2 * nn;
            int w = jpn / 3;
            int c = jpn - 3 * w;
            rowp[c * PLANEH + w] = v0;
            int c1 = c + 1, w1 = w;
            if (c1 == 3) { c1 = 0; w1++; }
            rowp[c1 * PLANEH + w1] = v1;
        }
    }
    __syncthreads();

    // ---- phase 2: Hilbert along h, 4 rows per thread ----
    const int wp = tid & 15;   // w-pair within half image
    const int ty = tid >> 4;   // 0..15; h = ty + 16m (all same parity)
    const int wl = 2 * wp;
    const int hp0 = (ty & 1) ^ 1;

    ull acc[4][3];
#pragma unroll
    for (int m = 0; m < 4; m++)
#pragma unroll
        for (int n = 0; n < 3; n++) acc[m][n] = 0ull;

#pragma unroll 4
    for (int i = 0; i < 32; i++) {
        int h2 = hp0 + 2 * i;
        float4 tv = tq[(ty - h2) & 63];
        ull tm[4];
        tm[0] = pack2(tv.x, tv.x);
        tm[1] = pack2(tv.y, tv.y);
        tm[2] = pack2(tv.z, tv.z);
        tm[3] = pack2(tv.w, tv.w);
        const float* rrow = rec_s + h2 * 32 + wl;
#pragma unroll
        for (int n = 0; n < 3; n++) {
            ull rv = *reinterpret_cast<const ull*>(rrow + n * PLANEH);
#pragma unroll
            for (int m = 0; m < 4; m++) fma2(acc[m][n], tm[m], rv);
        }
    }

    float* outg = out + (size_t)g * 24576;
    const int wg = wl + 32 * s;
#pragma unroll
    for (int m = 0; m < 4; m++) {
        int h = ty + 16 * m;
        const float* rrow = rec_s + h * 32 + wl;
        float r[3][2], a[3][2];
#pragma unroll
        for (int n = 0; n < 3; n++) {
            ull rv = *reinterpret_cast<const ull*>(rrow + n * PLANEH);
            unpack2(rv, r[n][0], r[n][1]);
            unpack2(acc[m][n], a[n][0], a[n][1]);
        }
        // two complete 6-float cells = 48B contiguous = 3x STG.128
        float* p = outg + h * 384 + wg * 6;  // 16B aligned (wg even)
        float4 v0, v1, v2;
        v0.x = r[0][0]; v0.y = r[1][0]; v0.z = r[2][0]; v0.w = a[0][0];
        v1.x = a[1][0]; v1.y = a[2][0]; v1.z = r[0][1]; v1.w = r[1][1];
        v2.x = r[2][1]; v2.y = a[0][1]; v2.z = a[1][1]; v2.w = a[2][1];
        *reinterpret_cast<float4*>(p)     = v0;
        *reinterpret_cast<float4*>(p + 4) = v1;
        *reinterpret_cast<float4*>(p + 8) = v2;
    }
}

extern "C" void kernel_launch(void* const* d_in, const int* in_sizes, int n_in,
                              void* d_out, int out_size) {
    const float* x  = (const float*)d_in[0];
    const float* w1 = (const float*)d_in[1];
    const float* b1 = (const float*)d_in[2];
    const float* w2 = (const float*)d_in[3];
    const float* b2 = (const float*)d_in[4];
    float* out = (float*)d_out;

    reduce_part_kernel<<<1536, 256>>>(x, w1, w2);
    finalize_kernel<<<12, 256>>>(b1, b2);
    fuse_kernel<<<4096, 256>>>(x, out);
}

// round 17
// speedup vs baseline: 1.1442x; 1.1442x over previous
#include <cuda_runtime.h>
#include <math.h>

typedef unsigned long long ull;
#define FULLMASK 0xffffffffu

// Per-batch 2x3 matrix M = Ginv * V^T, layout [b][k][c]
__device__ float g_M[3072 * 6];
// Packed weight pairs, planar: [f2][k], f2 pairs = (f0,f1),(f2,f3),(f4,f5)
__device__ ull g_wp[3 * 12288];

__device__ __forceinline__ ull pack2(float lo, float hi) {
    ull r;
    asm("mov.b64 %0, {%1, %2};" : "=l"(r) : "f"(lo), "f"(hi));
    return r;
}
__device__ __forceinline__ void fma2(ull& d, ull a, ull b) {
    asm("fma.rn.f32x2 %0, %1, %2, %0;" : "+l"(d) : "l"(a), "l"(b));
}
__device__ __forceinline__ void unpack2(ull v, float& lo, float& hi) {
    asm("mov.b64 {%0, %1}, %2;" : "=f"(lo), "=f"(hi) : "l"(v));
}

// ---------------------------------------------------------------------------
// Kernel A0: pack weights once into planar f32x2 pairs (288KB, L2-resident).
// ---------------------------------------------------------------------------
__global__ __launch_bounds__(256) void wpack_kernel(const float* __restrict__ w1,
                                                    const float* __restrict__ w2) {
    int i = blockIdx.x * 256 + threadIdx.x;  // 0..36863
    if (i >= 36864) return;
    int f2 = i / 12288;
    int k = i - f2 * 12288;
    float a, b;
    if (f2 == 0)      { a = __ldg(w1 + k * 3 + 0); b = __ldg(w1 + k * 3 + 1); }
    else if (f2 == 1) { a = __ldg(w1 + k * 3 + 2); b = __ldg(w2 + k * 3 + 0); }
    else              { a = __ldg(w2 + k * 3 + 1); b = __ldg(w2 + k * 3 + 2); }
    g_wp[f2 * 12288 + k] = pack2(a, b);
}

// ---------------------------------------------------------------------------
// Kernel A1: per-batch reductions -> M. 4 batches per CTA, full k, grid 768.
// NO smem weight staging: packed weight pairs stream from L2/L1 via g_wp.
// Inner iter: 3 LDG.64 (w) + 4 LDG.32 (x) + 4 pack + 12 fma2.
// ---------------------------------------------------------------------------
__global__ __launch_bounds__(256) void reduce_kernel(
    const float* __restrict__ x, const float* __restrict__ b1,
    const float* __restrict__ b2) {
    __shared__ float sp[1024];
    const int tid = threadIdx.x;
    const int b0 = blockIdx.x * 4;

    ull acc[4][3];
#pragma unroll
    for (int i = 0; i < 4; i++)
#pragma unroll
        for (int q = 0; q < 3; q++) acc[i][q] = 0ull;

    const float* xp0 = x + b0 * 12288 + tid;
    const float* xp1 = xp0 + 12288;
    const float* xp2 = xp1 + 12288;
    const float* xp3 = xp2 + 12288;
    const ull* wp = g_wp + tid;

#pragma unroll 2
    for (int i = 0; i < 48; i++) {
        ull wv0 = __ldg(wp);
        ull wv1 = __ldg(wp + 12288);
        ull wv2 = __ldg(wp + 24576);
        wp += 256;
        float x0 = __ldg(xp0), x1 = __ldg(xp1), x2 = __ldg(xp2), x3 = __ldg(xp3);
        xp0 += 256; xp1 += 256; xp2 += 256; xp3 += 256;
        ull xx0 = pack2(x0, x0), xx1 = pack2(x1, x1);
        ull xx2 = pack2(x2, x2), xx3 = pack2(x3, x3);
        fma2(acc[0][0], xx0, wv0); fma2(acc[0][1], xx0, wv1); fma2(acc[0][2], xx0, wv2);
        fma2(acc[1][0], xx1, wv0); fma2(acc[1][1], xx1, wv1); fma2(acc[1][2], xx1, wv2);
        fma2(acc[2][0], xx2, wv0); fma2(acc[2][1], xx2, wv1); fma2(acc[2][2], xx2, wv2);
        fma2(acc[3][0], xx3, wv0); fma2(acc[3][1], xx3, wv1); fma2(acc[3][2], xx3, wv2);
    }

    const int lane = tid & 31, wid = tid >> 5;
#pragma unroll
    for (int bb = 0; bb < 4; bb++)
#pragma unroll
        for (int q = 0; q < 3; q++) {
            float f0, f1;
            unpack2(acc[bb][q], f0, f1);
#pragma unroll
            for (int half = 0; half < 2; half++) {
                float v = half ? f1 : f0;
                v += __shfl_down_sync(FULLMASK, v, 16);
                v += __shfl_down_sync(FULLMASK, v, 8);
                v += __shfl_down_sync(FULLMASK, v, 4);
                v += __shfl_down_sync(FULLMASK, v, 2);
                v += __shfl_down_sync(FULLMASK, v, 1);
                if (lane == 0) sp[wid * 24 + bb * 6 + 2 * q + half] = v;
            }
        }
    __syncthreads();
    if (tid < 24) {
        float s = 0.0f;
#pragma unroll
        for (int w = 0; w < 8; w++) s += sp[w * 24 + tid];
        int f = tid % 6;
        s += (f < 3) ? __ldg(b1 + f) : __ldg(b2 + f - 3);
        sp[512 + tid] = s;
    }
    __syncthreads();
    if (tid < 4) {
        float V0[3], V1[3];
        float s0 = 1e-6f, s1 = 1e-6f;
#pragma unroll
        for (int c = 0; c < 3; c++) {
            V0[c] = sp[512 + tid * 6 + c];
            V1[c] = sp[512 + tid * 6 + 3 + c];
            s0 += fabsf(V0[c]);
            s1 += fabsf(V1[c]);
        }
        float r0 = 1.0f / s0, r1 = 1.0f / s1;
        float G00 = 0.f, G01 = 0.f, G11 = 0.f;
#pragma unroll
        for (int c = 0; c < 3; c++) {
            V0[c] *= r0;
            V1[c] *= r1;
            G00 += V0[c] * V0[c];
            G01 += V0[c] * V1[c];
            G11 += V1[c] * V1[c];
        }
        float det = G00 * G11 - G01 * G01;
        float rdet = 1.0f / det;
        float i00 = G11 * rdet, i01 = -G01 * rdet, i11 = G00 * rdet;
        int b = b0 + tid;
#pragma unroll
        for (int c = 0; c < 3; c++) {
            g_M[b * 6 + c]     = i00 * V0[c] + i01 * V1[c];
            g_M[b * 6 + 3 + c] = i01 * V0[c] + i11 * V1[c];
        }
    }
}

// ---------------------------------------------------------------------------
// Kernel C (R6-validated, 79.8us): one CTA (256 thr) per HALF output image.
// grid = 4096. Phase 1: rec = M x via LDG.128 into planar smem rec[3][64][32].
// Phase 2: 32-tap circulant Hilbert along h, 4 h-rows per thread, float4 tap
//          table (1 LDS.128 = 4 taps), fma.rn.f32x2, 3x STG.128 cell stores.
// ---------------------------------------------------------------------------
#define PLANEH 2056  // 64*32 + 8 pad (floats)

__global__ __launch_bounds__(256, 4) void fuse_kernel(const float* __restrict__ x,
                                                      float* __restrict__ out) {
    __shared__ float rec_s[3 * PLANEH];
    __shared__ float4 tq[64];  // {t[k], t[k+16], t[k+32], t[k+48]}
    const int gi = blockIdx.x;
    const int g = gi >> 1;
    const int s = gi & 1;
    const int tid = threadIdx.x;

    if (tid < 64) {
        float tv[4];
#pragma unroll
        for (int m = 0; m < 4; m++) {
            int k = (tid + 16 * m) & 63;
            float v = 0.0f;
            if (k & 1) {
                float a = 3.14159265358979323846f * (float)k / 64.0f;
                v = 0.03125f * (cosf(a) / sinf(a));
            }
            tv[m] = v;
        }
        float4 q; q.x = tv[0]; q.y = tv[1]; q.z = tv[2]; q.w = tv[3];
        tq[tid] = q;
    }

    const int b0 = (g * 3) >> 1;  // (g*12288)>>13
    float M0[6], M1[6];
#pragma unroll
    for (int i = 0; i < 6; i++) {
        M0[i] = __ldg(g_M + b0 * 6 + i);
        M1[i] = __ldg(g_M + (b0 + 1) * 6 + i);
    }

    // ---- phase 1: 768 chunks of 4 spatial positions (12 floats, 3x LDG.128)
#pragma unroll
    for (int it = 0; it < 3; it++) {
        int ci = tid + it * 256;
        int h = ci / 12;
        int cc = ci - h * 12;
        int jp0 = s * 96 + cc * 8;          // j offset within row (even)
        int F = g * 12288 + h * 192 + jp0;  // global flat index
        int b = F >> 13;
        int n0 = (F & 8191) >> 1;
        const float4* xp = (const float4*)(x + b * 12288 + 3 * n0);
        float4 q0 = __ldg(xp), q1 = __ldg(xp + 1), q2 = __ldg(xp + 2);
        float xv[12];
        xv[0] = q0.x; xv[1] = q0.y; xv[2]  = q0.z; xv[3]  = q0.w;
        xv[4] = q1.x; xv[5] = q1.y; xv[6]  = q1.z; xv[7]  = q1.w;
        xv[8] = q2.x; xv[9] = q2.y; xv[10] = q2.z; xv[11] = q2.w;
        bool useB = (b != b0);
        float m0 = useB ? M1[0] : M0[0];
        float m1 = useB ? M1[1] : M0[1];
        float m2 = useB ? M1[2] : M0[2];
        float m3 = useB ? M1[3] : M0[3];
        float m4 = useB ? M1[4] : M0[4];
        float m5 = useB ? M1[5] : M0[5];
        float* rowp = rec_s + h * 32 - 32 * s;
#pragma unroll
        for (int nn = 0; nn < 4; nn++) {
            float x0 = xv[3 * nn], x1 = xv[3 * nn + 1], x2 = xv[3 * nn + 2];
            float v0 = m0 * x0 + m1 * x1 + m2 * x2;
            float v1 = m3 * x0 + m4 * x1 + m5 * x2;
            int jpn = jp0 + 2 * nn;
            int w = jpn / 3;
            int c = jpn - 3 * w;
            rowp[c * PLANEH + w] = v0;
            int c1 = c + 1, w1 = w;
            if (c1 == 3) { c1 = 0; w1++; }
            rowp[c1 * PLANEH + w1] = v1;
        }
    }
    __syncthreads();

    // ---- phase 2: Hilbert along h, 4 rows per thread ----
    const int wp = tid & 15;   // w-pair within half image
    const int ty = tid >> 4;   // 0..15; h = ty + 16m (all same parity)
    const int wl = 2 * wp;
    const int hp0 = (ty & 1) ^ 1;

    ull acc[4][3];
#pragma unroll
    for (int m = 0; m < 4; m++)
#pragma unroll
        for (int n = 0; n < 3; n++) acc[m][n] = 0ull;

#pragma unroll 4
    for (int i = 0; i < 32; i++) {
        int h2 = hp0 + 2 * i;
        float4 tv = tq[(ty - h2) & 63];
        ull tm[4];
        tm[0] = pack2(tv.x, tv.x);
        tm[1] = pack2(tv.y, tv.y);
        tm[2] = pack2(tv.z, tv.z);
        tm[3] = pack2(tv.w, tv.w);
        const float* rrow = rec_s + h2 * 32 + wl;
#pragma unroll
        for (int n = 0; n < 3; n++) {
            ull rv = *reinterpret_cast<const ull*>(rrow + n * PLANEH);
#pragma unroll
            for (int m = 0; m < 4; m++) fma2(acc[m][n], tm[m], rv);
        }
    }

    float* outg = out + (size_t)g * 24576;
    const int wg = wl + 32 * s;
#pragma unroll
    for (int m = 0; m < 4; m++) {
        int h = ty + 16 * m;
        const float* rrow = rec_s + h * 32 + wl;
        float r[3][2], a[3][2];
#pragma unroll
        for (int n = 0; n < 3; n++) {
            ull rv = *reinterpret_cast<const ull*>(rrow + n * PLANEH);
            unpack2(rv, r[n][0], r[n][1]);
            unpack2(acc[m][n], a[n][0], a[n][1]);
        }
        // two complete 6-float cells = 48B contiguous = 3x STG.128
        float* p = outg + h * 384 + wg * 6;  // 16B aligned (wg even)
        float4 v0, v1, v2;
        v0.x = r[0][0]; v0.y = r[1][0]; v0.z = r[2][0]; v0.w = a[0][0];
        v1.x = a[1][0]; v1.y = a[2][0]; v1.z = r[0][1]; v1.w = r[1][1];
        v2.x = r[2][1]; v2.y = a[0][1]; v2.z = a[1][1]; v2.w = a[2][1];
        *reinterpret_cast<float4*>(p)     = v0;
        *reinterpret_cast<float4*>(p + 4) = v1;
        *reinterpret_cast<float4*>(p + 8) = v2;
    }
}

extern "C" void kernel_launch(void* const* d_in, const int* in_sizes, int n_in,
                              void* d_out, int out_size) {
    const float* x  = (const float*)d_in[0];
    const float* w1 = (const float*)d_in[1];
    const float* b1 = (const float*)d_in[2];
    const float* w2 = (const float*)d_in[3];
    const float* b2 = (const float*)d_in[4];
    float* out = (float*)d_out;

    wpack_kernel<<<144, 256>>>(w1, w2);
    reduce_kernel<<<768, 256>>>(x, b1, b2);
    fuse_kernel<<<4096, 256>>>(x, out);
}